// round 8
// baseline (speedup 1.0000x reference)
#include <cuda_runtime.h>
#include <math.h>

// Problem constants
#define BB 2
#define TT 1024
#define CC 1024
#define HH 16
#define DD 64
#define NCH 16          // chunks of 64 along T for linear attention
#define BHTD (BB*TT*CC)

// Scratch (static device globals; no allocation allowed)
__device__ float g_q [BHTD];
__device__ float g_k [BHTD];
__device__ float g_v [BHTD];
__device__ float g_ys[BHTD];                 // y_sharp
__device__ float g_yl[BHTD];                 // y_lin after attn LN
__device__ float g_kvc[BB*HH*NCH*DD*DD];     // per-chunk KV sums
__device__ float g_kvp[BB*HH*NCH*DD*DD];     // exclusive prefix of KV sums
__device__ float g_ksm[BB*HH*NCH*DD];        // per-chunk K sums
__device__ float g_kpr[BB*HH*NCH*DD];        // exclusive prefix of K sums

__device__ __forceinline__ float elup(float x) {       // elu(x)+1
    return x > 0.f ? x + 1.f : __expf(x);
}

// ---------------------------------------------------------------------------
// K1: qkv = x @ W^T + b   (M=2048, N=3072, K=1024), scatter into q/k/v [B,H,T,D]
// ---------------------------------------------------------------------------
__global__ void __launch_bounds__(256) k_qkv(const float* __restrict__ X,
                                             const float* __restrict__ W,
                                             const float* __restrict__ bias)
{
    __shared__ float As[16][132];
    __shared__ float Bs[16][132];
    const int tid = threadIdx.x;
    const int tx = tid & 15, ty = tid >> 4;
    const int m0 = blockIdx.y * 128;
    const int n0 = blockIdx.x * 128;
    float acc[8][8] = {};

    for (int k0 = 0; k0 < 1024; k0 += 16) {
#pragma unroll
        for (int u = 0; u < 2; ++u) {
            int id = tid + u * 256;
            int r  = id >> 2;
            int c4 = (id & 3) << 2;
            float4 a = *reinterpret_cast<const float4*>(X + (size_t)(m0 + r) * 1024 + k0 + c4);
            As[c4+0][r] = a.x; As[c4+1][r] = a.y; As[c4+2][r] = a.z; As[c4+3][r] = a.w;
            float4 bq = *reinterpret_cast<const float4*>(W + (size_t)(n0 + r) * 1024 + k0 + c4);
            Bs[c4+0][r] = bq.x; Bs[c4+1][r] = bq.y; Bs[c4+2][r] = bq.z; Bs[c4+3][r] = bq.w;
        }
        __syncthreads();
#pragma unroll
        for (int kk = 0; kk < 16; ++kk) {
            float ra[8], rb[8];
#pragma unroll
            for (int i = 0; i < 8; ++i) ra[i] = As[kk][ty*8 + i];
#pragma unroll
            for (int j = 0; j < 8; ++j) rb[j] = Bs[kk][j*16 + tx];
#pragma unroll
            for (int i = 0; i < 8; ++i)
#pragma unroll
                for (int j = 0; j < 8; ++j)
                    acc[i][j] = fmaf(ra[i], rb[j], acc[i][j]);
        }
        __syncthreads();
    }

    float bn[8];
#pragma unroll
    for (int j = 0; j < 8; ++j) bn[j] = bias[n0 + j*16 + tx];
#pragma unroll
    for (int i = 0; i < 8; ++i) {
        int m = m0 + ty*8 + i;
        int b = m >> 10, t = m & 1023;
#pragma unroll
        for (int j = 0; j < 8; ++j) {
            int n = n0 + j*16 + tx;
            int sec = n >> 10;
            int c = n & 1023;
            int h = c >> 6, d = c & 63;
            float* dst = (sec == 0) ? g_q : (sec == 1) ? g_k : g_v;
            dst[(((size_t)(b*HH + h)) * TT + t) * DD + d] = acc[i][j] + bn[j];
        }
    }
}

// ---------------------------------------------------------------------------
// K2: flash-style causal softmax attention, Br=Bc=64
// ---------------------------------------------------------------------------
__global__ void __launch_bounds__(256) k_flash()
{
    extern __shared__ float sm[];
    float* Qs = sm;                 // [64][65]
    float* Ks = sm + 4160;
    float* Vs = sm + 2*4160;
    float* Ps = sm + 3*4160;

    const int qb = blockIdx.x, h = blockIdx.y, b = blockIdx.z;
    const int bh = b*HH + h;
    const int q0 = qb * 64;
    const int tid = threadIdx.x, tx = tid & 15, ty = tid >> 4;
    const float* Qb = g_q + (size_t)bh * (TT*DD);
    const float* Kb = g_k + (size_t)bh * (TT*DD);
    const float* Vb = g_v + (size_t)bh * (TT*DD);

    for (int e = tid; e < 4096; e += 256) {
        int r = e >> 6, c = e & 63;
        Qs[r*65 + c] = Qb[(size_t)(q0 + r)*64 + c] * 0.125f;
    }

    float acc[4][4] = {};
    float m_i[4], l_i[4] = {};
#pragma unroll
    for (int i = 0; i < 4; ++i) m_i[i] = -1e30f;

    for (int kt = 0; kt <= qb; ++kt) {
        int k0 = kt * 64;
        for (int e = tid; e < 4096; e += 256) {
            int r = e >> 6, c = e & 63;
            Ks[r*65 + c] = Kb[(size_t)(k0 + r)*64 + c];
            Vs[r*65 + c] = Vb[(size_t)(k0 + r)*64 + c];
        }
        __syncthreads();

        float s[4][4] = {};
        for (int d = 0; d < 64; ++d) {
            float qv[4], kv[4];
#pragma unroll
            for (int i = 0; i < 4; ++i) qv[i] = Qs[(ty*4 + i)*65 + d];
#pragma unroll
            for (int j = 0; j < 4; ++j) kv[j] = Ks[(j*16 + tx)*65 + d];
#pragma unroll
            for (int i = 0; i < 4; ++i)
#pragma unroll
                for (int j = 0; j < 4; ++j)
                    s[i][j] = fmaf(qv[i], kv[j], s[i][j]);
        }

        if (kt == qb) {
#pragma unroll
            for (int i = 0; i < 4; ++i) {
                int row = q0 + ty*4 + i;
#pragma unroll
                for (int j = 0; j < 4; ++j) {
                    int col = k0 + j*16 + tx;
                    if (col > row) s[i][j] = -1e30f;
                }
            }
        }

#pragma unroll
        for (int i = 0; i < 4; ++i) {
            float mx = fmaxf(fmaxf(s[i][0], s[i][1]), fmaxf(s[i][2], s[i][3]));
#pragma unroll
            for (int off = 8; off; off >>= 1)
                mx = fmaxf(mx, __shfl_xor_sync(0xffffffffu, mx, off));
            float mnew = fmaxf(m_i[i], mx);
            float scl  = __expf(m_i[i] - mnew);
            m_i[i] = mnew;
            float rs = 0.f;
#pragma unroll
            for (int j = 0; j < 4; ++j) { s[i][j] = __expf(s[i][j] - mnew); rs += s[i][j]; }
#pragma unroll
            for (int off = 8; off; off >>= 1)
                rs += __shfl_xor_sync(0xffffffffu, rs, off);
            l_i[i] = l_i[i] * scl + rs;
#pragma unroll
            for (int j = 0; j < 4; ++j) acc[i][j] *= scl;
#pragma unroll
            for (int j = 0; j < 4; ++j) Ps[(ty*4 + i)*65 + j*16 + tx] = s[i][j];
        }
        __syncthreads();

        for (int c = 0; c < 64; ++c) {
            float pv[4], vv[4];
#pragma unroll
            for (int i = 0; i < 4; ++i) pv[i] = Ps[(ty*4 + i)*65 + c];
#pragma unroll
            for (int j = 0; j < 4; ++j) vv[j] = Vs[c*65 + j*16 + tx];
#pragma unroll
            for (int i = 0; i < 4; ++i)
#pragma unroll
                for (int j = 0; j < 4; ++j)
                    acc[i][j] = fmaf(pv[i], vv[j], acc[i][j]);
        }
        __syncthreads();
    }

#pragma unroll
    for (int i = 0; i < 4; ++i) {
        int row = q0 + ty*4 + i;
        float inv = 1.f / l_i[i];
#pragma unroll
        for (int j = 0; j < 4; ++j)
            g_ys[((size_t)bh * TT + row)*64 + j*16 + tx] = acc[i][j] * inv;
    }
}

// ---------------------------------------------------------------------------
// K3a: per-chunk KV outer-product sums + K sums
// ---------------------------------------------------------------------------
__global__ void __launch_bounds__(256) k_linA()
{
    extern __shared__ float sm[];
    float* Kps = sm;          // [64][65] feature-mapped K
    float* Vss = sm + 4160;

    const int ch = blockIdx.x, h = blockIdx.y, b = blockIdx.z;
    const int bh = b*HH + h;
    const int t0 = ch * 64;
    const int tid = threadIdx.x, tx = tid & 15, ty = tid >> 4;
    const float* Kb = g_k + (size_t)bh * (TT*DD);
    const float* Vb = g_v + (size_t)bh * (TT*DD);

    for (int e = tid; e < 4096; e += 256) {
        int r = e >> 6, c = e & 63;
        Kps[r*65 + c] = elup(Kb[(size_t)(t0 + r)*64 + c] * 0.125f);
        Vss[r*65 + c] = Vb[(size_t)(t0 + r)*64 + c];
    }
    __syncthreads();

    float acc[4][4] = {};
    for (int t = 0; t < 64; ++t) {
        float a[4], v[4];
#pragma unroll
        for (int i = 0; i < 4; ++i) a[i] = Kps[t*65 + ty*4 + i];
#pragma unroll
        for (int j = 0; j < 4; ++j) v[j] = Vss[t*65 + j*16 + tx];
#pragma unroll
        for (int i = 0; i < 4; ++i)
#pragma unroll
            for (int j = 0; j < 4; ++j)
                acc[i][j] = fmaf(a[i], v[j], acc[i][j]);
    }
    size_t ob = ((size_t)bh * NCH + ch) * 4096;
#pragma unroll
    for (int i = 0; i < 4; ++i)
#pragma unroll
        for (int j = 0; j < 4; ++j)
            g_kvc[ob + (ty*4 + i)*64 + j*16 + tx] = acc[i][j];

    if (tid < 64) {
        float s = 0.f;
        for (int t = 0; t < 64; ++t) s += Kps[t*65 + tid];
        g_ksm[((size_t)bh * NCH + ch)*64 + tid] = s;
    }
}

// ---------------------------------------------------------------------------
// K3b: exclusive prefix over chunks (per b,h)
// ---------------------------------------------------------------------------
__global__ void __launch_bounds__(256) k_linB()
{
    const int bh = blockIdx.x;
    const size_t base = (size_t)bh * NCH * 4096;
    float run[16];
#pragma unroll
    for (int u = 0; u < 16; ++u) run[u] = 0.f;
    for (int c = 0; c < NCH; ++c) {
        size_t cb = base + (size_t)c * 4096;
#pragma unroll
        for (int u = 0; u < 16; ++u) {
            int idx = threadIdx.x + u * 256;
            g_kvp[cb + idx] = run[u];
            run[u] += g_kvc[cb + idx];
        }
    }
    if (threadIdx.x < 64) {
        float r2 = 0.f;
        size_t kb = (size_t)bh * NCH * 64;
        for (int c = 0; c < NCH; ++c) {
            g_kpr[kb + c*64 + threadIdx.x] = r2;
            r2 += g_ksm[kb + c*64 + threadIdx.x];
        }
    }
}

// ---------------------------------------------------------------------------
// K3c: inter+intra chunk linear attention + fused per-row LN over D
// ---------------------------------------------------------------------------
__global__ void __launch_bounds__(256) k_linC(const float* __restrict__ ang,
                                              const float* __restrict__ anb)
{
    extern __shared__ float sm[];
    float* Qps = sm;               // [64][65]
    float* Kps = sm + 4160;
    float* Vss = sm + 2*4160;
    float* Sps = sm + 3*4160;      // prefix state [d][e]
    float* Ps  = sm + 4*4160;      // intra scores
    float* kpre = sm + 5*4160;     // [64]
    float* sg   = kpre + 64;
    float* sb   = sg + 64;

    const int ch = blockIdx.x, h = blockIdx.y, b = blockIdx.z;
    const int bh = b*HH + h;
    const int t0 = ch * 64;
    const int tid = threadIdx.x, tx = tid & 15, ty = tid >> 4;
    const float* Qb = g_q + (size_t)bh * (TT*DD);
    const float* Kb = g_k + (size_t)bh * (TT*DD);
    const float* Vb = g_v + (size_t)bh * (TT*DD);
    const size_t pbase = ((size_t)bh * NCH + ch) * 4096;

    for (int e = tid; e < 4096; e += 256) {
        int r = e >> 6, c = e & 63;
        Qps[r*65 + c] = elup(Qb[(size_t)(t0 + r)*64 + c] * 0.125f);
        Kps[r*65 + c] = elup(Kb[(size_t)(t0 + r)*64 + c] * 0.125f);
        Vss[r*65 + c] = Vb[(size_t)(t0 + r)*64 + c];
        Sps[r*65 + c] = g_kvp[pbase + e];
    }
    if (tid < 64) {
        kpre[tid] = g_kpr[((size_t)bh * NCH + ch)*64 + tid];
        sg[tid] = ang[tid];
        sb[tid] = anb[tid];
    }
    __syncthreads();

    float acc[4][4] = {};   // numerator
    float sc[4][4]  = {};   // intra scores
    for (int d = 0; d < 64; ++d) {
        float qv[4], sv[4], kv[4];
#pragma unroll
        for (int i = 0; i < 4; ++i) qv[i] = Qps[(ty*4 + i)*65 + d];
#pragma unroll
        for (int j = 0; j < 4; ++j) sv[j] = Sps[d*65 + j*16 + tx];
#pragma unroll
        for (int j = 0; j < 4; ++j) kv[j] = Kps[(j*16 + tx)*65 + d];
#pragma unroll
        for (int i = 0; i < 4; ++i)
#pragma unroll
            for (int j = 0; j < 4; ++j) {
                acc[i][j] = fmaf(qv[i], sv[j], acc[i][j]);
                sc[i][j]  = fmaf(qv[i], kv[j], sc[i][j]);
            }
    }

    float den[4];
#pragma unroll
    for (int i = 0; i < 4; ++i) {
        int t_loc = ty*4 + i;
        float rs = 0.f;
#pragma unroll
        for (int j = 0; j < 4; ++j) {
            int s_loc = j*16 + tx;
            if (s_loc > t_loc) sc[i][j] = 0.f;
            rs += sc[i][j];
            Ps[t_loc*65 + s_loc] = sc[i][j];
        }
#pragma unroll
        for (int off = 8; off; off >>= 1)
            rs += __shfl_xor_sync(0xffffffffu, rs, off);
        float dq = 0.f;
        for (int d = 0; d < 64; ++d) dq = fmaf(Qps[t_loc*65 + d], kpre[d], dq);
        den[i] = dq + rs + 1e-4f;
    }
    __syncthreads();

    for (int s = 0; s < 64; ++s) {
        float pv[4], vv[4];
#pragma unroll
        for (int i = 0; i < 4; ++i) pv[i] = Ps[(ty*4 + i)*65 + s];
#pragma unroll
        for (int j = 0; j < 4; ++j) vv[j] = Vss[s*65 + j*16 + tx];
#pragma unroll
        for (int i = 0; i < 4; ++i)
#pragma unroll
            for (int j = 0; j < 4; ++j)
                acc[i][j] = fmaf(pv[i], vv[j], acc[i][j]);
    }

#pragma unroll
    for (int i = 0; i < 4; ++i) {
        float inv = 1.f / den[i];
        float y[4], smm = 0.f, sq = 0.f;
#pragma unroll
        for (int j = 0; j < 4; ++j) {
            y[j] = acc[i][j] * inv;
            smm += y[j];
            sq  += y[j]*y[j];
        }
#pragma unroll
        for (int off = 8; off; off >>= 1) {
            smm += __shfl_xor_sync(0xffffffffu, smm, off);
            sq  += __shfl_xor_sync(0xffffffffu, sq,  off);
        }
        float mean = smm * (1.f/64.f);
        float var  = sq * (1.f/64.f) - mean*mean;
        float rstd = rsqrtf(var + 1e-5f);
        int row = t0 + ty*4 + i;
#pragma unroll
        for (int j = 0; j < 4; ++j) {
            int e = j*16 + tx;
            g_yl[((size_t)bh * TT + row)*64 + e] = (y[j] - mean)*rstd*sg[e] + sb[e];
        }
    }
}

// ---------------------------------------------------------------------------
// K4: combine + out LN + pre LN + block mix + grid bilinear + reverse + bias
// ---------------------------------------------------------------------------
__device__ __forceinline__ float2 block_reduce2(float a, float b, float* red)
{
#pragma unroll
    for (int off = 16; off; off >>= 1) {
        a += __shfl_xor_sync(0xffffffffu, a, off);
        b += __shfl_xor_sync(0xffffffffu, b, off);
    }
    int w = threadIdx.x >> 5;
    if ((threadIdx.x & 31) == 0) { red[w] = a; red[8 + w] = b; }
    __syncthreads();
    float ta = 0.f, tb = 0.f;
#pragma unroll
    for (int i = 0; i < 8; ++i) { ta += red[i]; tb += red[8 + i]; }
    __syncthreads();
    return make_float2(ta, tb);
}

__global__ void __launch_bounds__(256) k_proj(const float* __restrict__ fgate,
                                              const float* __restrict__ og,
                                              const float* __restrict__ ob,
                                              const float* __restrict__ pg,
                                              const float* __restrict__ pb,
                                              const float* __restrict__ bw,
                                              const float* __restrict__ wrow,
                                              const float* __restrict__ wcol,
                                              const float* __restrict__ palpha,
                                              const float* __restrict__ pbias,
                                              float* __restrict__ out)
{
    extern __shared__ float sm[];
    float* xns   = sm;            // 1024
    float* mixed = sm + 1024;     // 1024
    float* zz    = sm + 2048;     // 1024
    float* wcs   = sm + 3072;     // 1024
    float* wrT   = sm + 4096;     // 1024 (transposed)
    float* bws   = sm + 5120;     // 16384
    float* red   = sm + 21504;    // 16

    const int t = blockIdx.x, b = blockIdx.y;
    const int tid = threadIdx.x;
    const float fg = fgate[0];
    const float alpha = 1.f / (1.f + __expf(-fg));
    const float pa = palpha[0];

    for (int i = tid; i < 16384; i += 256) bws[i] = bw[i];
    for (int i = tid; i < 1024; i += 256) {
        wcs[i] = wcol[i];
        wrT[(i & 31)*32 + (i >> 5)] = wrow[i];   // wrT[c][r] = wrow[r][c]
    }

    // combine + LN(out_norm)
    float v[4];
    float s1 = 0.f, q1 = 0.f;
#pragma unroll
    for (int u = 0; u < 4; ++u) {
        int c = tid + u*256;
        int h = c >> 6, d = c & 63;
        size_t idx = ((size_t)(b*HH + h) * TT + t)*64 + d;
        float val = alpha * g_ys[idx] + (1.f - alpha) * g_yl[idx];
        v[u] = val;
        s1 += val; q1 += val*val;
    }
    float2 r1 = block_reduce2(s1, q1, red);
    float m1 = r1.x * (1.f/1024.f);
    float rs1 = rsqrtf(r1.y * (1.f/1024.f) - m1*m1 + 1e-5f);

    // LN(proj_pre) on the result
    float w[4];
    float s2 = 0.f, q2 = 0.f;
#pragma unroll
    for (int u = 0; u < 4; ++u) {
        int c = tid + u*256;
        float val = (v[u] - m1) * rs1 * og[c] + ob[c];
        w[u] = val;
        s2 += val; q2 += val*val;
    }
    float2 r2 = block_reduce2(s2, q2, red);
    float m2 = r2.x * (1.f/1024.f);
    float rs2 = rsqrtf(r2.y * (1.f/1024.f) - m2*m2 + 1e-5f);
#pragma unroll
    for (int u = 0; u < 4; ++u) {
        int c = tid + u*256;
        xns[c] = (w[u] - m2) * rs2 * pg[c] + pb[c];
    }
    __syncthreads();

    // block mix + first grid matmul
#pragma unroll
    for (int u = 0; u < 4; ++u) {
        int c = tid + u*256;
        int g = c >> 4, j = c & 15;
        float s = 0.f;
#pragma unroll
        for (int i = 0; i < 16; ++i)
            s = fmaf(xns[g*16 + i], bws[(g*16 + i)*16 + j], s);
        mixed[c] = s;

        int gi = c >> 5, cc = c & 31;
        float z = 0.f;
#pragma unroll
        for (int jj = 0; jj < 32; ++jj)
            z = fmaf(xns[gi*32 + jj], wcs[jj*32 + cc], z);
        zz[c] = z;
    }
    __syncthreads();

    // second grid matmul + reverse + bias
    float* orow = out + ((size_t)b * TT + t) * CC;
#pragma unroll
    for (int u = 0; u < 4; ++u) {
        int c = tid + u*256;
        int gi = c >> 5, r = c & 31;
        float z2 = 0.f;
#pragma unroll
        for (int cc = 0; cc < 32; ++cc)
            z2 = fmaf(zz[gi*32 + cc], wrT[cc*32 + r], z2);
        orow[c] = mixed[1023 - c] + pa * z2 + pbias[c];
    }
}

// ---------------------------------------------------------------------------
extern "C" void kernel_launch(void* const* d_in, const int* in_sizes, int n_in,
                              void* d_out, int out_size)
{
    (void)in_sizes; (void)n_in; (void)out_size;
    const float* x    = (const float*)d_in[0];
    const float* W    = (const float*)d_in[1];
    const float* cb   = (const float*)d_in[2];
    const float* fg   = (const float*)d_in[3];
    const float* ang  = (const float*)d_in[4];
    const float* anb  = (const float*)d_in[5];
    const float* og   = (const float*)d_in[6];
    const float* ob   = (const float*)d_in[7];
    const float* pg   = (const float*)d_in[8];
    const float* pb   = (const float*)d_in[9];
    const float* bw   = (const float*)d_in[10];
    const float* wr   = (const float*)d_in[11];
    const float* wc   = (const float*)d_in[12];
    const float* pa   = (const float*)d_in[13];
    const float* pbias= (const float*)d_in[14];
    float* out = (float*)d_out;

    cudaFuncSetAttribute(k_flash, cudaFuncAttributeMaxDynamicSharedMemorySize, 66560);
    cudaFuncSetAttribute(k_linC,  cudaFuncAttributeMaxDynamicSharedMemorySize, 83968);
    cudaFuncSetAttribute(k_proj,  cudaFuncAttributeMaxDynamicSharedMemorySize, 86080);

    k_qkv <<<dim3(24, 16),        256>>>(x, W, cb);
    k_flash<<<dim3(16, 16, 2),    256, 66560>>>();
    k_linA <<<dim3(16, 16, 2),    256, 33280>>>();
    k_linB <<<32,                 256>>>();
    k_linC <<<dim3(16, 16, 2),    256, 83968>>>(ang, anb);
    k_proj <<<dim3(1024, 2),      256, 86080>>>(fg, og, ob, pg, pb, bw, wr, wc, pa, pbias, out);
}

// round 10
// speedup vs baseline: 2.4690x; 2.4690x over previous
#include <cuda_runtime.h>
#include <cuda_bf16.h>
#include <math.h>

// Problem constants
#define BB 2
#define TT 1024
#define CC 1024
#define HH 16
#define DD 64
#define NCH 16
#define BHTD (BB*TT*CC)

// Scratch (static device globals; no allocation allowed)
__device__ float g_q [BHTD];
__device__ float g_k [BHTD];
__device__ float g_v [BHTD];
__device__ float g_ys[BHTD];
__device__ float g_yl[BHTD];
__device__ float g_kvc[BB*HH*NCH*DD*DD];
__device__ float g_kvp[BB*HH*NCH*DD*DD];
__device__ float g_ksm[BB*HH*NCH*DD];
__device__ float g_kpr[BB*HH*NCH*DD];
// bf16 split copies for tensor-core GEMM
__device__ __nv_bfloat16 g_xhi[2048*1024];
__device__ __nv_bfloat16 g_xlo[2048*1024];
__device__ __nv_bfloat16 g_whi[3072*1024];
__device__ __nv_bfloat16 g_wlo[3072*1024];

__device__ __forceinline__ float elup(float x) {
    return x > 0.f ? x + 1.f : __expf(x);
}

__device__ __forceinline__ void mma16816(float& c0, float& c1, float& c2, float& c3,
    unsigned a0, unsigned a1, unsigned a2, unsigned a3, unsigned b0, unsigned b1)
{
    asm volatile("mma.sync.aligned.m16n8k16.row.col.f32.bf16.bf16.f32 "
        "{%0,%1,%2,%3}, {%4,%5,%6,%7}, {%8,%9}, {%0,%1,%2,%3};\n"
        : "+f"(c0), "+f"(c1), "+f"(c2), "+f"(c3)
        : "r"(a0), "r"(a1), "r"(a2), "r"(a3), "r"(b0), "r"(b1));
}

// ---------------------------------------------------------------------------
// K0: split-convert X and W into bf16 hi/lo
// ---------------------------------------------------------------------------
__global__ void __launch_bounds__(256) k_cvt(const float* __restrict__ X,
                                             const float* __restrict__ W)
{
    int stride = gridDim.x * 256;
    for (int i = blockIdx.x*256 + threadIdx.x; i < 2048*1024; i += stride) {
        float x = X[i];
        __nv_bfloat16 h = __float2bfloat16(x);
        g_xhi[i] = h;
        g_xlo[i] = __float2bfloat16(x - __bfloat162float(h));
    }
    for (int i = blockIdx.x*256 + threadIdx.x; i < 3072*1024; i += stride) {
        float x = W[i];
        __nv_bfloat16 h = __float2bfloat16(x);
        g_whi[i] = h;
        g_wlo[i] = __float2bfloat16(x - __bfloat162float(h));
    }
}

// ---------------------------------------------------------------------------
// K1: qkv = x @ W^T + b via bf16x3 mma.sync, scatter into q/k/v [B,H,T,D]
// CTA tile 128x128, 8 warps (4 m x 2 n), warp tile 32x64.
// ---------------------------------------------------------------------------
__global__ void __launch_bounds__(256) k_qkv(const float* __restrict__ bias)
{
    extern __shared__ unsigned char smraw[];
    __nv_bfloat16* sA_hi = (__nv_bfloat16*)smraw;      // [128][72]
    __nv_bfloat16* sA_lo = sA_hi + 128*72;
    __nv_bfloat16* sB_hi = sA_lo + 128*72;
    __nv_bfloat16* sB_lo = sB_hi + 128*72;

    const int tid  = threadIdx.x;
    const int lane = tid & 31, warp = tid >> 5;
    const int wm = warp & 3, wn = warp >> 2;
    const int g = lane >> 2, tg = lane & 3;
    const int m0 = blockIdx.y * 128, n0 = blockIdx.x * 128;

    float acc[2][8][4];
#pragma unroll
    for (int mf = 0; mf < 2; ++mf)
#pragma unroll
        for (int nf = 0; nf < 8; ++nf)
#pragma unroll
            for (int q = 0; q < 4; ++q) acc[mf][nf][q] = 0.f;

    float bn[8][2];
#pragma unroll
    for (int nf = 0; nf < 8; ++nf) {
        int n = n0 + wn*64 + nf*8 + 2*tg;
        bn[nf][0] = bias[n];
        bn[nf][1] = bias[n+1];
    }

    const unsigned* a_hi32 = (const unsigned*)sA_hi;
    const unsigned* a_lo32 = (const unsigned*)sA_lo;
    const unsigned* b_hi32 = (const unsigned*)sB_hi;
    const unsigned* b_lo32 = (const unsigned*)sB_lo;

    for (int kc = 0; kc < 16; ++kc) {
        int k0 = kc * 64;
        __syncthreads();
#pragma unroll
        for (int it = 0; it < 4; ++it) {
            int idx = tid + it*256;
            int r = idx >> 3, cg = idx & 7;
            size_t sa = (size_t)(m0 + r)*1024 + k0 + cg*8;
            size_t sb = (size_t)(n0 + r)*1024 + k0 + cg*8;
            ((uint4*)sA_hi)[r*9 + cg] = *(const uint4*)(g_xhi + sa);
            ((uint4*)sA_lo)[r*9 + cg] = *(const uint4*)(g_xlo + sa);
            ((uint4*)sB_hi)[r*9 + cg] = *(const uint4*)(g_whi + sb);
            ((uint4*)sB_lo)[r*9 + cg] = *(const uint4*)(g_wlo + sb);
        }
        __syncthreads();
#pragma unroll
        for (int kk = 0; kk < 4; ++kk) {
            unsigned ah[2][4], al[2][4];
#pragma unroll
            for (int mf = 0; mf < 2; ++mf) {
                int base = (wm*32 + mf*16 + g)*36 + kk*8 + tg;
                ah[mf][0] = a_hi32[base];       ah[mf][1] = a_hi32[base + 288];
                ah[mf][2] = a_hi32[base + 4];   ah[mf][3] = a_hi32[base + 292];
                al[mf][0] = a_lo32[base];       al[mf][1] = a_lo32[base + 288];
                al[mf][2] = a_lo32[base + 4];   al[mf][3] = a_lo32[base + 292];
            }
#pragma unroll
            for (int nf = 0; nf < 8; ++nf) {
                int bbase = (wn*64 + nf*8 + g)*36 + kk*8 + tg;
                unsigned bh0 = b_hi32[bbase], bh1 = b_hi32[bbase + 4];
                unsigned bl0 = b_lo32[bbase], bl1 = b_lo32[bbase + 4];
#pragma unroll
                for (int mf = 0; mf < 2; ++mf) {
                    mma16816(acc[mf][nf][0], acc[mf][nf][1], acc[mf][nf][2], acc[mf][nf][3],
                             ah[mf][0], ah[mf][1], ah[mf][2], ah[mf][3], bh0, bh1);
                    mma16816(acc[mf][nf][0], acc[mf][nf][1], acc[mf][nf][2], acc[mf][nf][3],
                             ah[mf][0], ah[mf][1], ah[mf][2], ah[mf][3], bl0, bl1);
                    mma16816(acc[mf][nf][0], acc[mf][nf][1], acc[mf][nf][2], acc[mf][nf][3],
                             al[mf][0], al[mf][1], al[mf][2], al[mf][3], bh0, bh1);
                }
            }
        }
    }

    // epilogue: scatter with bias
#pragma unroll
    for (int mf = 0; mf < 2; ++mf) {
#pragma unroll
        for (int nf = 0; nf < 8; ++nf) {
            int row0 = m0 + wm*32 + mf*16 + g;
            int n    = n0 + wn*64 + nf*8 + 2*tg;
#pragma unroll
            for (int q = 0; q < 4; ++q) {
                int m  = row0 + (q >> 1)*8;
                int nn = n + (q & 1);
                int b = m >> 10, t = m & 1023;
                int sec = nn >> 10, c = nn & 1023;
                int h = c >> 6, d = c & 63;
                float* dst = (sec == 0) ? g_q : (sec == 1) ? g_k : g_v;
                dst[(((size_t)(b*HH + h)) * TT + t) * DD + d] = acc[mf][nf][q] + bn[nf][q & 1];
            }
        }
    }
}

// ---------------------------------------------------------------------------
// K2: flash-style causal softmax attention, Br=Bc=64
// ---------------------------------------------------------------------------
__global__ void __launch_bounds__(256) k_flash()
{
    extern __shared__ float sm[];
    float* Qs = sm;                 // [64][65]
    float* Ks = sm + 4160;
    float* Vs = sm + 2*4160;
    float* Ps = sm + 3*4160;

    const int qb = blockIdx.x, h = blockIdx.y, b = blockIdx.z;
    const int bh = b*HH + h;
    const int q0 = qb * 64;
    const int tid = threadIdx.x, tx = tid & 15, ty = tid >> 4;
    const float* Qb = g_q + (size_t)bh * (TT*DD);
    const float* Kb = g_k + (size_t)bh * (TT*DD);
    const float* Vb = g_v + (size_t)bh * (TT*DD);

    for (int e = tid; e < 4096; e += 256) {
        int r = e >> 6, c = e & 63;
        Qs[r*65 + c] = Qb[(size_t)(q0 + r)*64 + c] * 0.125f;
    }

    float acc[4][4] = {};
    float m_i[4], l_i[4] = {};
#pragma unroll
    for (int i = 0; i < 4; ++i) m_i[i] = -1e30f;

    for (int kt = 0; kt <= qb; ++kt) {
        int k0 = kt * 64;
        for (int e = tid; e < 4096; e += 256) {
            int r = e >> 6, c = e & 63;
            Ks[r*65 + c] = Kb[(size_t)(k0 + r)*64 + c];
            Vs[r*65 + c] = Vb[(size_t)(k0 + r)*64 + c];
        }
        __syncthreads();

        float s[4][4] = {};
        for (int d = 0; d < 64; ++d) {
            float qv[4], kv[4];
#pragma unroll
            for (int i = 0; i < 4; ++i) qv[i] = Qs[(ty*4 + i)*65 + d];
#pragma unroll
            for (int j = 0; j < 4; ++j) kv[j] = Ks[(j*16 + tx)*65 + d];
#pragma unroll
            for (int i = 0; i < 4; ++i)
#pragma unroll
                for (int j = 0; j < 4; ++j)
                    s[i][j] = fmaf(qv[i], kv[j], s[i][j]);
        }

        if (kt == qb) {
#pragma unroll
            for (int i = 0; i < 4; ++i) {
                int row = q0 + ty*4 + i;
#pragma unroll
                for (int j = 0; j < 4; ++j) {
                    int col = k0 + j*16 + tx;
                    if (col > row) s[i][j] = -1e30f;
                }
            }
        }

#pragma unroll
        for (int i = 0; i < 4; ++i) {
            float mx = fmaxf(fmaxf(s[i][0], s[i][1]), fmaxf(s[i][2], s[i][3]));
#pragma unroll
            for (int off = 8; off; off >>= 1)
                mx = fmaxf(mx, __shfl_xor_sync(0xffffffffu, mx, off));
            float mnew = fmaxf(m_i[i], mx);
            float scl  = __expf(m_i[i] - mnew);
            m_i[i] = mnew;
            float rs = 0.f;
#pragma unroll
            for (int j = 0; j < 4; ++j) { s[i][j] = __expf(s[i][j] - mnew); rs += s[i][j]; }
#pragma unroll
            for (int off = 8; off; off >>= 1)
                rs += __shfl_xor_sync(0xffffffffu, rs, off);
            l_i[i] = l_i[i] * scl + rs;
#pragma unroll
            for (int j = 0; j < 4; ++j) acc[i][j] *= scl;
#pragma unroll
            for (int j = 0; j < 4; ++j) Ps[(ty*4 + i)*65 + j*16 + tx] = s[i][j];
        }
        __syncthreads();

        for (int c = 0; c < 64; ++c) {
            float pv[4], vv[4];
#pragma unroll
            for (int i = 0; i < 4; ++i) pv[i] = Ps[(ty*4 + i)*65 + c];
#pragma unroll
            for (int j = 0; j < 4; ++j) vv[j] = Vs[c*65 + j*16 + tx];
#pragma unroll
            for (int i = 0; i < 4; ++i)
#pragma unroll
                for (int j = 0; j < 4; ++j)
                    acc[i][j] = fmaf(pv[i], vv[j], acc[i][j]);
        }
        __syncthreads();
    }

#pragma unroll
    for (int i = 0; i < 4; ++i) {
        int row = q0 + ty*4 + i;
        float inv = 1.f / l_i[i];
#pragma unroll
        for (int j = 0; j < 4; ++j)
            g_ys[((size_t)bh * TT + row)*64 + j*16 + tx] = acc[i][j] * inv;
    }
}

// ---------------------------------------------------------------------------
// K3a: per-chunk KV outer-product sums + K sums
// ---------------------------------------------------------------------------
__global__ void __launch_bounds__(256) k_linA()
{
    extern __shared__ float sm[];
    float* Kps = sm;          // [64][65]
    float* Vss = sm + 4160;

    const int ch = blockIdx.x, h = blockIdx.y, b = blockIdx.z;
    const int bh = b*HH + h;
    const int t0 = ch * 64;
    const int tid = threadIdx.x, tx = tid & 15, ty = tid >> 4;
    const float* Kb = g_k + (size_t)bh * (TT*DD);
    const float* Vb = g_v + (size_t)bh * (TT*DD);

    for (int e = tid; e < 4096; e += 256) {
        int r = e >> 6, c = e & 63;
        Kps[r*65 + c] = elup(Kb[(size_t)(t0 + r)*64 + c] * 0.125f);
        Vss[r*65 + c] = Vb[(size_t)(t0 + r)*64 + c];
    }
    __syncthreads();

    float acc[4][4] = {};
    for (int t = 0; t < 64; ++t) {
        float a[4], v[4];
#pragma unroll
        for (int i = 0; i < 4; ++i) a[i] = Kps[t*65 + ty*4 + i];
#pragma unroll
        for (int j = 0; j < 4; ++j) v[j] = Vss[t*65 + j*16 + tx];
#pragma unroll
        for (int i = 0; i < 4; ++i)
#pragma unroll
            for (int j = 0; j < 4; ++j)
                acc[i][j] = fmaf(a[i], v[j], acc[i][j]);
    }
    size_t ob = ((size_t)bh * NCH + ch) * 4096;
#pragma unroll
    for (int i = 0; i < 4; ++i)
#pragma unroll
        for (int j = 0; j < 4; ++j)
            g_kvc[ob + (ty*4 + i)*64 + j*16 + tx] = acc[i][j];

    if (tid < 64) {
        float s = 0.f;
        for (int t = 0; t < 64; ++t) s += Kps[t*65 + tid];
        g_ksm[((size_t)bh * NCH + ch)*64 + tid] = s;
    }
}

// ---------------------------------------------------------------------------
// K3b: parallel exclusive prefix over chunks (per bh, per element)
// grid (17, 32): x<16 -> kvc groups of 256 elements; x==16 -> ksm (64 elems)
// ---------------------------------------------------------------------------
__global__ void __launch_bounds__(256) k_scan()
{
    const int bh = blockIdx.y;
    if (blockIdx.x < 16) {
        size_t base = (size_t)bh * NCH * 4096 + blockIdx.x * 256 + threadIdx.x;
        float v[16];
#pragma unroll
        for (int c = 0; c < 16; ++c) v[c] = g_kvc[base + (size_t)c*4096];
        float run = 0.f;
#pragma unroll
        for (int c = 0; c < 16; ++c) {
            g_kvp[base + (size_t)c*4096] = run;
            run += v[c];
        }
    } else if (threadIdx.x < 64) {
        size_t kb = (size_t)bh * NCH * 64 + threadIdx.x;
        float v[16];
#pragma unroll
        for (int c = 0; c < 16; ++c) v[c] = g_ksm[kb + c*64];
        float run = 0.f;
#pragma unroll
        for (int c = 0; c < 16; ++c) {
            g_kpr[kb + c*64] = run;
            run += v[c];
        }
    }
}

// ---------------------------------------------------------------------------
// K3c: inter+intra chunk linear attention + fused per-row LN over D
// ---------------------------------------------------------------------------
__global__ void __launch_bounds__(256) k_linC(const float* __restrict__ ang,
                                              const float* __restrict__ anb)
{
    extern __shared__ float sm[];
    float* Qps = sm;               // [64][65]
    float* Kps = sm + 4160;
    float* Vss = sm + 2*4160;
    float* Sps = sm + 3*4160;
    float* Ps  = sm + 4*4160;
    float* kpre = sm + 5*4160;
    float* sg   = kpre + 64;
    float* sb   = sg + 64;

    const int ch = blockIdx.x, h = blockIdx.y, b = blockIdx.z;
    const int bh = b*HH + h;
    const int t0 = ch * 64;
    const int tid = threadIdx.x, tx = tid & 15, ty = tid >> 4;
    const float* Qb = g_q + (size_t)bh * (TT*DD);
    const float* Kb = g_k + (size_t)bh * (TT*DD);
    const float* Vb = g_v + (size_t)bh * (TT*DD);
    const size_t pbase = ((size_t)bh * NCH + ch) * 4096;

    for (int e = tid; e < 4096; e += 256) {
        int r = e >> 6, c = e & 63;
        Qps[r*65 + c] = elup(Qb[(size_t)(t0 + r)*64 + c] * 0.125f);
        Kps[r*65 + c] = elup(Kb[(size_t)(t0 + r)*64 + c] * 0.125f);
        Vss[r*65 + c] = Vb[(size_t)(t0 + r)*64 + c];
        Sps[r*65 + c] = g_kvp[pbase + e];
    }
    if (tid < 64) {
        kpre[tid] = g_kpr[((size_t)bh * NCH + ch)*64 + tid];
        sg[tid] = ang[tid];
        sb[tid] = anb[tid];
    }
    __syncthreads();

    float acc[4][4] = {};
    float sc[4][4]  = {};
    for (int d = 0; d < 64; ++d) {
        float qv[4], sv[4], kv[4];
#pragma unroll
        for (int i = 0; i < 4; ++i) qv[i] = Qps[(ty*4 + i)*65 + d];
#pragma unroll
        for (int j = 0; j < 4; ++j) sv[j] = Sps[d*65 + j*16 + tx];
#pragma unroll
        for (int j = 0; j < 4; ++j) kv[j] = Kps[(j*16 + tx)*65 + d];
#pragma unroll
        for (int i = 0; i < 4; ++i)
#pragma unroll
            for (int j = 0; j < 4; ++j) {
                acc[i][j] = fmaf(qv[i], sv[j], acc[i][j]);
                sc[i][j]  = fmaf(qv[i], kv[j], sc[i][j]);
            }
    }

    float den[4];
#pragma unroll
    for (int i = 0; i < 4; ++i) {
        int t_loc = ty*4 + i;
        float rs = 0.f;
#pragma unroll
        for (int j = 0; j < 4; ++j) {
            int s_loc = j*16 + tx;
            if (s_loc > t_loc) sc[i][j] = 0.f;
            rs += sc[i][j];
            Ps[t_loc*65 + s_loc] = sc[i][j];
        }
#pragma unroll
        for (int off = 8; off; off >>= 1)
            rs += __shfl_xor_sync(0xffffffffu, rs, off);
        float dq = 0.f;
        for (int d = 0; d < 64; ++d) dq = fmaf(Qps[t_loc*65 + d], kpre[d], dq);
        den[i] = dq + rs + 1e-4f;
    }
    __syncthreads();

    for (int s = 0; s < 64; ++s) {
        float pv[4], vv[4];
#pragma unroll
        for (int i = 0; i < 4; ++i) pv[i] = Ps[(ty*4 + i)*65 + s];
#pragma unroll
        for (int j = 0; j < 4; ++j) vv[j] = Vss[s*65 + j*16 + tx];
#pragma unroll
        for (int i = 0; i < 4; ++i)
#pragma unroll
            for (int j = 0; j < 4; ++j)
                acc[i][j] = fmaf(pv[i], vv[j], acc[i][j]);
    }

#pragma unroll
    for (int i = 0; i < 4; ++i) {
        float inv = 1.f / den[i];
        float y[4], smm = 0.f, sq = 0.f;
#pragma unroll
        for (int j = 0; j < 4; ++j) {
            y[j] = acc[i][j] * inv;
            smm += y[j];
            sq  += y[j]*y[j];
        }
#pragma unroll
        for (int off = 8; off; off >>= 1) {
            smm += __shfl_xor_sync(0xffffffffu, smm, off);
            sq  += __shfl_xor_sync(0xffffffffu, sq,  off);
        }
        float mean = smm * (1.f/64.f);
        float var  = sq * (1.f/64.f) - mean*mean;
        float rstd = rsqrtf(var + 1e-5f);
        int row = t0 + ty*4 + i;
#pragma unroll
        for (int j = 0; j < 4; ++j) {
            int e = j*16 + tx;
            g_yl[((size_t)bh * TT + row)*64 + e] = (y[j] - mean)*rstd*sg[e] + sb[e];
        }
    }
}

// ---------------------------------------------------------------------------
// K4: combine + out LN + pre LN + block mix + grid bilinear + reverse + bias
// ---------------------------------------------------------------------------
__device__ __forceinline__ float2 block_reduce2(float a, float b, float* red)
{
#pragma unroll
    for (int off = 16; off; off >>= 1) {
        a += __shfl_xor_sync(0xffffffffu, a, off);
        b += __shfl_xor_sync(0xffffffffu, b, off);
    }
    int w = threadIdx.x >> 5;
    if ((threadIdx.x & 31) == 0) { red[w] = a; red[8 + w] = b; }
    __syncthreads();
    float ta = 0.f, tb = 0.f;
#pragma unroll
    for (int i = 0; i < 8; ++i) { ta += red[i]; tb += red[8 + i]; }
    __syncthreads();
    return make_float2(ta, tb);
}

__global__ void __launch_bounds__(256) k_proj(const float* __restrict__ fgate,
                                              const float* __restrict__ og,
                                              const float* __restrict__ ob,
                                              const float* __restrict__ pg,
                                              const float* __restrict__ pb,
                                              const float* __restrict__ bw,
                                              const float* __restrict__ wrow,
                                              const float* __restrict__ wcol,
                                              const float* __restrict__ palpha,
                                              const float* __restrict__ pbias,
                                              float* __restrict__ out)
{
    extern __shared__ float sm[];
    float* xns   = sm;
    float* mixed = sm + 1024;
    float* zz    = sm + 2048;
    float* wcs   = sm + 3072;
    float* wrT   = sm + 4096;
    float* bws   = sm + 5120;
    float* red   = sm + 21504;

    const int t = blockIdx.x, b = blockIdx.y;
    const int tid = threadIdx.x;
    const float fg = fgate[0];
    const float alpha = 1.f / (1.f + __expf(-fg));
    const float pa = palpha[0];

    for (int i = tid; i < 16384; i += 256) bws[i] = bw[i];
    for (int i = tid; i < 1024; i += 256) {
        wcs[i] = wcol[i];
        wrT[(i & 31)*32 + (i >> 5)] = wrow[i];
    }

    float v[4];
    float s1 = 0.f, q1 = 0.f;
#pragma unroll
    for (int u = 0; u < 4; ++u) {
        int c = tid + u*256;
        int h = c >> 6, d = c & 63;
        size_t idx = ((size_t)(b*HH + h) * TT + t)*64 + d;
        float val = alpha * g_ys[idx] + (1.f - alpha) * g_yl[idx];
        v[u] = val;
        s1 += val; q1 += val*val;
    }
    float2 r1 = block_reduce2(s1, q1, red);
    float m1 = r1.x * (1.f/1024.f);
    float rs1 = rsqrtf(r1.y * (1.f/1024.f) - m1*m1 + 1e-5f);

    float w[4];
    float s2 = 0.f, q2 = 0.f;
#pragma unroll
    for (int u = 0; u < 4; ++u) {
        int c = tid + u*256;
        float val = (v[u] - m1) * rs1 * og[c] + ob[c];
        w[u] = val;
        s2 += val; q2 += val*val;
    }
    float2 r2 = block_reduce2(s2, q2, red);
    float m2 = r2.x * (1.f/1024.f);
    float rs2 = rsqrtf(r2.y * (1.f/1024.f) - m2*m2 + 1e-5f);
#pragma unroll
    for (int u = 0; u < 4; ++u) {
        int c = tid + u*256;
        xns[c] = (w[u] - m2) * rs2 * pg[c] + pb[c];
    }
    __syncthreads();

#pragma unroll
    for (int u = 0; u < 4; ++u) {
        int c = tid + u*256;
        int g = c >> 4, j = c & 15;
        float s = 0.f;
#pragma unroll
        for (int i = 0; i < 16; ++i)
            s = fmaf(xns[g*16 + i], bws[(g*16 + i)*16 + j], s);
        mixed[c] = s;

        int gi = c >> 5, cc = c & 31;
        float z = 0.f;
#pragma unroll
        for (int jj = 0; jj < 32; ++jj)
            z = fmaf(xns[gi*32 + jj], wcs[jj*32 + cc], z);
        zz[c] = z;
    }
    __syncthreads();

    float* orow = out + ((size_t)b * TT + t) * CC;
#pragma unroll
    for (int u = 0; u < 4; ++u) {
        int c = tid + u*256;
        int gi = c >> 5, r = c & 31;
        float z2 = 0.f;
#pragma unroll
        for (int cc = 0; cc < 32; ++cc)
            z2 = fmaf(zz[gi*32 + cc], wrT[cc*32 + r], z2);
        orow[c] = mixed[1023 - c] + pa * z2 + pbias[c];
    }
}

// ---------------------------------------------------------------------------
extern "C" void kernel_launch(void* const* d_in, const int* in_sizes, int n_in,
                              void* d_out, int out_size)
{
    (void)in_sizes; (void)n_in; (void)out_size;
    const float* x    = (const float*)d_in[0];
    const float* W    = (const float*)d_in[1];
    const float* cb   = (const float*)d_in[2];
    const float* fg   = (const float*)d_in[3];
    const float* ang  = (const float*)d_in[4];
    const float* anb  = (const float*)d_in[5];
    const float* og   = (const float*)d_in[6];
    const float* ob   = (const float*)d_in[7];
    const float* pg   = (const float*)d_in[8];
    const float* pb   = (const float*)d_in[9];
    const float* bw   = (const float*)d_in[10];
    const float* wr   = (const float*)d_in[11];
    const float* wc   = (const float*)d_in[12];
    const float* pa   = (const float*)d_in[13];
    const float* pbias= (const float*)d_in[14];
    float* out = (float*)d_out;

    cudaFuncSetAttribute(k_qkv,   cudaFuncAttributeMaxDynamicSharedMemorySize, 73728);
    cudaFuncSetAttribute(k_flash, cudaFuncAttributeMaxDynamicSharedMemorySize, 66560);
    cudaFuncSetAttribute(k_linC,  cudaFuncAttributeMaxDynamicSharedMemorySize, 83968);
    cudaFuncSetAttribute(k_proj,  cudaFuncAttributeMaxDynamicSharedMemorySize, 86080);

    k_cvt  <<<1184,               256>>>(x, W);
    k_qkv  <<<dim3(24, 16),       256, 73728>>>(cb);
    k_flash<<<dim3(16, 16, 2),    256, 66560>>>();
    k_linA <<<dim3(16, 16, 2),    256, 33280>>>();
    k_scan <<<dim3(17, 32),       256>>>();
    k_linC <<<dim3(16, 16, 2),    256, 83968>>>(ang, anb);
    k_proj <<<dim3(1024, 2),      256, 86080>>>(fg, og, ob, pg, pb, bw, wr, wc, pa, pbias, out);
}

// round 15
// speedup vs baseline: 2.7577x; 1.1170x over previous
#include <cuda_runtime.h>
#include <cuda_bf16.h>
#include <math.h>

#define BB 2
#define TT 1024
#define CC 1024
#define HH 16
#define DD 64
#define NCH 16
#define BHTD (BB*TT*CC)

__device__ float g_q [BHTD];
__device__ float g_k [BHTD];
__device__ float g_v [BHTD];
__device__ float g_ys[BHTD];
__device__ float g_yl[BHTD];
__device__ float g_kvc[BB*HH*NCH*DD*DD];
__device__ float g_kvp[BB*HH*NCH*DD*DD];
__device__ float g_ksm[BB*HH*NCH*DD];
__device__ float g_kpr[BB*HH*NCH*DD];
// bf16 split copies
__device__ __nv_bfloat16 g_xhi[2048*1024];
__device__ __nv_bfloat16 g_xlo[2048*1024];
__device__ __nv_bfloat16 g_whi[3072*1024];
__device__ __nv_bfloat16 g_wlo[3072*1024];
__device__ __nv_bfloat16 g_qhi[BHTD];   // q*scale, split
__device__ __nv_bfloat16 g_qlo[BHTD];
__device__ __nv_bfloat16 g_khi[BHTD];
__device__ __nv_bfloat16 g_klo[BHTD];
__device__ __nv_bfloat16 g_vthi[BHTD];  // v transposed [b,h,d,t], split
__device__ __nv_bfloat16 g_vtlo[BHTD];

__device__ __forceinline__ float elup(float x) {
    return x > 0.f ? x + 1.f : __expf(x);
}

__device__ __forceinline__ void mma16816(float& c0, float& c1, float& c2, float& c3,
    unsigned a0, unsigned a1, unsigned a2, unsigned a3, unsigned b0, unsigned b1)
{
    asm volatile("mma.sync.aligned.m16n8k16.row.col.f32.bf16.bf16.f32 "
        "{%0,%1,%2,%3}, {%4,%5,%6,%7}, {%8,%9}, {%0,%1,%2,%3};\n"
        : "+f"(c0), "+f"(c1), "+f"(c2), "+f"(c3)
        : "r"(a0), "r"(a1), "r"(a2), "r"(a3), "r"(b0), "r"(b1));
}

// ---------------------------------------------------------------------------
// K0: split-convert X and W into bf16 hi/lo
// ---------------------------------------------------------------------------
__global__ void __launch_bounds__(256) k_cvt(const float* __restrict__ X,
                                             const float* __restrict__ W)
{
    int stride = gridDim.x * 256;
    for (int i = blockIdx.x*256 + threadIdx.x; i < 2048*1024; i += stride) {
        float x = X[i];
        __nv_bfloat16 h = __float2bfloat16(x);
        g_xhi[i] = h;
        g_xlo[i] = __float2bfloat16(x - __bfloat162float(h));
    }
    for (int i = blockIdx.x*256 + threadIdx.x; i < 3072*1024; i += stride) {
        float x = W[i];
        __nv_bfloat16 h = __float2bfloat16(x);
        g_whi[i] = h;
        g_wlo[i] = __float2bfloat16(x - __bfloat162float(h));
    }
}

// ---------------------------------------------------------------------------
// K1: qkv GEMM via bf16x3 mma.sync; scatter fp32 q/k/v + bf16 splits
// ---------------------------------------------------------------------------
__global__ void __launch_bounds__(256) k_qkv(const float* __restrict__ bias)
{
    extern __shared__ unsigned char smraw[];
    __nv_bfloat16* sA_hi = (__nv_bfloat16*)smraw;      // [128][72]
    __nv_bfloat16* sA_lo = sA_hi + 128*72;
    __nv_bfloat16* sB_hi = sA_lo + 128*72;
    __nv_bfloat16* sB_lo = sB_hi + 128*72;

    const int tid  = threadIdx.x;
    const int lane = tid & 31, warp = tid >> 5;
    const int wm = warp & 3, wn = warp >> 2;
    const int g = lane >> 2, tg = lane & 3;
    const int m0 = blockIdx.y * 128, n0 = blockIdx.x * 128;

    float acc[2][8][4];
#pragma unroll
    for (int mf = 0; mf < 2; ++mf)
#pragma unroll
        for (int nf = 0; nf < 8; ++nf)
#pragma unroll
            for (int q = 0; q < 4; ++q) acc[mf][nf][q] = 0.f;

    float bn[8][2];
#pragma unroll
    for (int nf = 0; nf < 8; ++nf) {
        int n = n0 + wn*64 + nf*8 + 2*tg;
        bn[nf][0] = bias[n];
        bn[nf][1] = bias[n+1];
    }

    const unsigned* a_hi32 = (const unsigned*)sA_hi;
    const unsigned* a_lo32 = (const unsigned*)sA_lo;
    const unsigned* b_hi32 = (const unsigned*)sB_hi;
    const unsigned* b_lo32 = (const unsigned*)sB_lo;

    for (int kc = 0; kc < 16; ++kc) {
        int k0 = kc * 64;
        __syncthreads();
#pragma unroll
        for (int it = 0; it < 4; ++it) {
            int idx = tid + it*256;
            int r = idx >> 3, cg = idx & 7;
            size_t sa = (size_t)(m0 + r)*1024 + k0 + cg*8;
            size_t sb = (size_t)(n0 + r)*1024 + k0 + cg*8;
            ((uint4*)sA_hi)[r*9 + cg] = *(const uint4*)(g_xhi + sa);
            ((uint4*)sA_lo)[r*9 + cg] = *(const uint4*)(g_xlo + sa);
            ((uint4*)sB_hi)[r*9 + cg] = *(const uint4*)(g_whi + sb);
            ((uint4*)sB_lo)[r*9 + cg] = *(const uint4*)(g_wlo + sb);
        }
        __syncthreads();
#pragma unroll
        for (int kk = 0; kk < 4; ++kk) {
            unsigned ah[2][4], al[2][4];
#pragma unroll
            for (int mf = 0; mf < 2; ++mf) {
                int base = (wm*32 + mf*16 + g)*36 + kk*8 + tg;
                ah[mf][0] = a_hi32[base];       ah[mf][1] = a_hi32[base + 288];
                ah[mf][2] = a_hi32[base + 4];   ah[mf][3] = a_hi32[base + 292];
                al[mf][0] = a_lo32[base];       al[mf][1] = a_lo32[base + 288];
                al[mf][2] = a_lo32[base + 4];   al[mf][3] = a_lo32[base + 292];
            }
#pragma unroll
            for (int nf = 0; nf < 8; ++nf) {
                int bbase = (wn*64 + nf*8 + g)*36 + kk*8 + tg;
                unsigned bh0 = b_hi32[bbase], bh1 = b_hi32[bbase + 4];
                unsigned bl0 = b_lo32[bbase], bl1 = b_lo32[bbase + 4];
#pragma unroll
                for (int mf = 0; mf < 2; ++mf) {
                    mma16816(acc[mf][nf][0], acc[mf][nf][1], acc[mf][nf][2], acc[mf][nf][3],
                             ah[mf][0], ah[mf][1], ah[mf][2], ah[mf][3], bh0, bh1);
                    mma16816(acc[mf][nf][0], acc[mf][nf][1], acc[mf][nf][2], acc[mf][nf][3],
                             ah[mf][0], ah[mf][1], ah[mf][2], ah[mf][3], bl0, bl1);
                    mma16816(acc[mf][nf][0], acc[mf][nf][1], acc[mf][nf][2], acc[mf][nf][3],
                             al[mf][0], al[mf][1], al[mf][2], al[mf][3], bh0, bh1);
                }
            }
        }
    }

    // epilogue: scatter fp32 + bf16 splits
#pragma unroll
    for (int mf = 0; mf < 2; ++mf) {
#pragma unroll
        for (int nf = 0; nf < 8; ++nf) {
            int row0 = m0 + wm*32 + mf*16 + g;
            int n    = n0 + wn*64 + nf*8 + 2*tg;
#pragma unroll
            for (int q = 0; q < 4; ++q) {
                int m  = row0 + (q >> 1)*8;
                int nn = n + (q & 1);
                int b = m >> 10, t = m & 1023;
                int sec = nn >> 10, c = nn & 1023;
                int h = c >> 6, d = c & 63;
                float val = acc[mf][nf][q] + bn[nf][q & 1];
                size_t idx = (((size_t)(b*HH + h)) * TT + t) * DD + d;
                if (sec == 0) {
                    g_q[idx] = val;
                    float qs = val * 0.125f;
                    __nv_bfloat16 hbits = __float2bfloat16(qs);
                    g_qhi[idx] = hbits;
                    g_qlo[idx] = __float2bfloat16(qs - __bfloat162float(hbits));
                } else if (sec == 1) {
                    g_k[idx] = val;
                    __nv_bfloat16 hbits = __float2bfloat16(val);
                    g_khi[idx] = hbits;
                    g_klo[idx] = __float2bfloat16(val - __bfloat162float(hbits));
                } else {
                    g_v[idx] = val;
                    __nv_bfloat16 hbits = __float2bfloat16(val);
                    size_t tidx = (((size_t)(b*HH + h)) * DD + d) * TT + t;
                    g_vthi[tidx] = hbits;
                    g_vtlo[tidx] = __float2bfloat16(val - __bfloat162float(hbits));
                }
            }
        }
    }
}

// ---------------------------------------------------------------------------
// K2: flash attention, Br=Bc=64, QK^T and PV on tensor cores (bf16 split)
// ---------------------------------------------------------------------------
__global__ void __launch_bounds__(256) k_flash()
{
    extern __shared__ float sm[];
    float* Ss = sm;                               // [64][65] fp32 scores
    __nv_bfloat16* bb = (__nv_bfloat16*)(sm + 4160);
    __nv_bfloat16* Qhi = bb;                      // each [64][72]
    __nv_bfloat16* Qlo = bb + 4608;
    __nv_bfloat16* Khi = bb + 2*4608;
    __nv_bfloat16* Klo = bb + 3*4608;
    __nv_bfloat16* Vth = bb + 4*4608;
    __nv_bfloat16* Vtl = bb + 5*4608;
    __nv_bfloat16* Phi = bb + 6*4608;
    __nv_bfloat16* Plo = bb + 7*4608;
    float* sclr = (float*)(bb + 8*4608);          // [64]
    float* lrow = sclr + 64;                      // [64]

    const int qb = blockIdx.x, h = blockIdx.y, b = blockIdx.z;
    const int bh = b*HH + h;
    const int q0 = qb * 64;
    const int tid = threadIdx.x;
    const int lane = tid & 31, warp = tid >> 5;
    const int wm = warp & 3, wn = warp >> 2;      // 4x2 warp grid, tiles 16x32
    const int g = lane >> 2, tg = lane & 3;
    const int tx = tid & 15, ty = tid >> 4;

    const __nv_bfloat16* Qhg = g_qhi + (size_t)bh * (TT*DD);
    const __nv_bfloat16* Qlg = g_qlo + (size_t)bh * (TT*DD);
    const __nv_bfloat16* Khg = g_khi + (size_t)bh * (TT*DD);
    const __nv_bfloat16* Klg = g_klo + (size_t)bh * (TT*DD);
    const __nv_bfloat16* Vhg = g_vthi + (size_t)bh * (DD*TT);
    const __nv_bfloat16* Vlg = g_vtlo + (size_t)bh * (DD*TT);

    // load Q tile once
#pragma unroll
    for (int it = 0; it < 2; ++it) {
        int idx = tid + it*256;
        int r = idx >> 3, cg = idx & 7;
        ((uint4*)Qhi)[r*9 + cg] = *(const uint4*)(Qhg + (size_t)(q0 + r)*64 + cg*8);
        ((uint4*)Qlo)[r*9 + cg] = *(const uint4*)(Qlg + (size_t)(q0 + r)*64 + cg*8);
    }

    const unsigned* qh32 = (const unsigned*)Qhi;
    const unsigned* ql32 = (const unsigned*)Qlo;
    const unsigned* kh32 = (const unsigned*)Khi;
    const unsigned* kl32 = (const unsigned*)Klo;
    const unsigned* vh32 = (const unsigned*)Vth;
    const unsigned* vl32 = (const unsigned*)Vtl;
    const unsigned* ph32 = (const unsigned*)Phi;
    const unsigned* pl32 = (const unsigned*)Plo;

    float m_i[4], l_i[4] = {};
#pragma unroll
    for (int i = 0; i < 4; ++i) m_i[i] = -1e30f;
    float acc[4][4];                               // O fragments: nf x {c0..c3}
#pragma unroll
    for (int nf = 0; nf < 4; ++nf)
#pragma unroll
        for (int q = 0; q < 4; ++q) acc[nf][q] = 0.f;

    for (int kt = 0; kt <= qb; ++kt) {
        int k0 = kt * 64;
        __syncthreads();   // prior PV reads of K/Vt/P done
#pragma unroll
        for (int it = 0; it < 2; ++it) {
            int idx = tid + it*256;
            int r = idx >> 3, cg = idx & 7;
            ((uint4*)Khi)[r*9 + cg] = *(const uint4*)(Khg + (size_t)(k0 + r)*64 + cg*8);
            ((uint4*)Klo)[r*9 + cg] = *(const uint4*)(Klg + (size_t)(k0 + r)*64 + cg*8);
            ((uint4*)Vth)[r*9 + cg] = *(const uint4*)(Vhg + (size_t)r*TT + k0 + cg*8);
            ((uint4*)Vtl)[r*9 + cg] = *(const uint4*)(Vlg + (size_t)r*TT + k0 + cg*8);
        }
        __syncthreads();

        // S = Q*scale @ K^T  (warp tile 16x32)
        float sf[4][4];
#pragma unroll
        for (int nf = 0; nf < 4; ++nf)
#pragma unroll
            for (int q = 0; q < 4; ++q) sf[nf][q] = 0.f;
#pragma unroll
        for (int kk = 0; kk < 4; ++kk) {
            int base = (wm*16 + g)*36 + kk*8 + tg;
            unsigned ah0 = qh32[base], ah1 = qh32[base + 288];
            unsigned ah2 = qh32[base + 4], ah3 = qh32[base + 292];
            unsigned al0 = ql32[base], al1 = ql32[base + 288];
            unsigned al2 = ql32[base + 4], al3 = ql32[base + 292];
#pragma unroll
            for (int nf = 0; nf < 4; ++nf) {
                int bbase = (wn*32 + nf*8 + g)*36 + kk*8 + tg;
                unsigned bh0 = kh32[bbase], bh1 = kh32[bbase + 4];
                unsigned bl0 = kl32[bbase], bl1 = kl32[bbase + 4];
                mma16816(sf[nf][0], sf[nf][1], sf[nf][2], sf[nf][3],
                         ah0, ah1, ah2, ah3, bh0, bh1);
                mma16816(sf[nf][0], sf[nf][1], sf[nf][2], sf[nf][3],
                         ah0, ah1, ah2, ah3, bl0, bl1);
                mma16816(sf[nf][0], sf[nf][1], sf[nf][2], sf[nf][3],
                         al0, al1, al2, al3, bh0, bh1);
            }
        }
#pragma unroll
        for (int nf = 0; nf < 4; ++nf) {
            int r0 = wm*16 + g, c0 = wn*32 + nf*8 + 2*tg;
            Ss[r0*65 + c0]       = sf[nf][0];
            Ss[r0*65 + c0 + 1]   = sf[nf][1];
            Ss[(r0+8)*65 + c0]     = sf[nf][2];
            Ss[(r0+8)*65 + c0 + 1] = sf[nf][3];
        }
        __syncthreads();

        // online softmax (threads own rows ty*4+i across all iterations)
#pragma unroll
        for (int i = 0; i < 4; ++i) {
            int row = ty*4 + i;
            float s[4];
#pragma unroll
            for (int j = 0; j < 4; ++j) {
                int col = tx + 16*j;
                float sv = Ss[row*65 + col];
                if (kt == qb && col > row) sv = -1e30f;
                s[j] = sv;
            }
            float mx = fmaxf(fmaxf(s[0], s[1]), fmaxf(s[2], s[3]));
#pragma unroll
            for (int off = 8; off; off >>= 1)
                mx = fmaxf(mx, __shfl_xor_sync(0xffffffffu, mx, off));
            float mnew = fmaxf(m_i[i], mx);
            float sclv = __expf(m_i[i] - mnew);
            m_i[i] = mnew;
            float rs = 0.f;
#pragma unroll
            for (int j = 0; j < 4; ++j) {
                float p = __expf(s[j] - mnew);
                rs += p;
                int col = tx + 16*j;
                __nv_bfloat16 phb = __float2bfloat16(p);
                Phi[row*72 + col] = phb;
                Plo[row*72 + col] = __float2bfloat16(p - __bfloat162float(phb));
            }
#pragma unroll
            for (int off = 8; off; off >>= 1)
                rs += __shfl_xor_sync(0xffffffffu, rs, off);
            l_i[i] = l_i[i] * sclv + rs;
            if (tx == 0) sclr[row] = sclv;
        }
        __syncthreads();

        // rescale O fragments, then O += P @ V
        {
            int r0 = wm*16 + g, r1 = r0 + 8;
            float f0 = sclr[r0], f1 = sclr[r1];
#pragma unroll
            for (int nf = 0; nf < 4; ++nf) {
                acc[nf][0] *= f0; acc[nf][1] *= f0;
                acc[nf][2] *= f1; acc[nf][3] *= f1;
            }
        }
#pragma unroll
        for (int kk = 0; kk < 4; ++kk) {
            int base = (wm*16 + g)*36 + kk*8 + tg;
            unsigned ah0 = ph32[base], ah1 = ph32[base + 288];
            unsigned ah2 = ph32[base + 4], ah3 = ph32[base + 292];
            unsigned al0 = pl32[base], al1 = pl32[base + 288];
            unsigned al2 = pl32[base + 4], al3 = pl32[base + 292];
#pragma unroll
            for (int nf = 0; nf < 4; ++nf) {
                int bbase = (wn*32 + nf*8 + g)*36 + kk*8 + tg;
                unsigned bh0 = vh32[bbase], bh1 = vh32[bbase + 4];
                unsigned bl0 = vl32[bbase], bl1 = vl32[bbase + 4];
                mma16816(acc[nf][0], acc[nf][1], acc[nf][2], acc[nf][3],
                         ah0, ah1, ah2, ah3, bh0, bh1);
                mma16816(acc[nf][0], acc[nf][1], acc[nf][2], acc[nf][3],
                         al0, al1, al2, al3, bh0, bh1);
                mma16816(acc[nf][0], acc[nf][1], acc[nf][2], acc[nf][3],
                         ah0, ah1, ah2, ah3, bl0, bl1);
            }
        }
    }

    // finalize: divide by l and store O
    if (tx == 0) {
#pragma unroll
        for (int i = 0; i < 4; ++i) lrow[ty*4 + i] = l_i[i];
    }
    __syncthreads();
    {
        int r0 = wm*16 + g, r1 = r0 + 8;
        float inv0 = 1.f / lrow[r0], inv1 = 1.f / lrow[r1];
        float* Ob = g_ys + (size_t)bh * (TT*DD);
#pragma unroll
        for (int nf = 0; nf < 4; ++nf) {
            int col = wn*32 + nf*8 + 2*tg;
            Ob[(size_t)(q0 + r0)*64 + col]     = acc[nf][0]*inv0;
            Ob[(size_t)(q0 + r0)*64 + col + 1] = acc[nf][1]*inv0;
            Ob[(size_t)(q0 + r1)*64 + col]     = acc[nf][2]*inv1;
            Ob[(size_t)(q0 + r1)*64 + col + 1] = acc[nf][3]*inv1;
        }
    }
}

// ---------------------------------------------------------------------------
// K3a: per-chunk KV outer-product sums + K sums
// ---------------------------------------------------------------------------
__global__ void __launch_bounds__(256) k_linA()
{
    extern __shared__ float sm[];
    float* Kps = sm;          // [64][65]
    float* Vss = sm + 4160;

    const int ch = blockIdx.x, h = blockIdx.y, b = blockIdx.z;
    const int bh = b*HH + h;
    const int t0 = ch * 64;
    const int tid = threadIdx.x, tx = tid & 15, ty = tid >> 4;
    const float* Kb = g_k + (size_t)bh * (TT*DD);
    const float* Vb = g_v + (size_t)bh * (TT*DD);

    for (int e = tid; e < 4096; e += 256) {
        int r = e >> 6, c = e & 63;
        Kps[r*65 + c] = elup(Kb[(size_t)(t0 + r)*64 + c] * 0.125f);
        Vss[r*65 + c] = Vb[(size_t)(t0 + r)*64 + c];
    }
    __syncthreads();

    float acc[4][4] = {};
    for (int t = 0; t < 64; ++t) {
        float a[4], v[4];
#pragma unroll
        for (int i = 0; i < 4; ++i) a[i] = Kps[t*65 + ty*4 + i];
#pragma unroll
        for (int j = 0; j < 4; ++j) v[j] = Vss[t*65 + j*16 + tx];
#pragma unroll
        for (int i = 0; i < 4; ++i)
#pragma unroll
            for (int j = 0; j < 4; ++j)
                acc[i][j] = fmaf(a[i], v[j], acc[i][j]);
    }
    size_t ob = ((size_t)bh * NCH + ch) * 4096;
#pragma unroll
    for (int i = 0; i < 4; ++i)
#pragma unroll
        for (int j = 0; j < 4; ++j)
            g_kvc[ob + (ty*4 + i)*64 + j*16 + tx] = acc[i][j];

    if (tid < 64) {
        float s = 0.f;
        for (int t = 0; t < 64; ++t) s += Kps[t*65 + tid];
        g_ksm[((size_t)bh * NCH + ch)*64 + tid] = s;
    }
}

// ---------------------------------------------------------------------------
// K3b: parallel exclusive prefix over chunks
// ---------------------------------------------------------------------------
__global__ void __launch_bounds__(256) k_scan()
{
    const int bh = blockIdx.y;
    if (blockIdx.x < 16) {
        size_t base = (size_t)bh * NCH * 4096 + blockIdx.x * 256 + threadIdx.x;
        float v[16];
#pragma unroll
        for (int c = 0; c < 16; ++c) v[c] = g_kvc[base + (size_t)c*4096];
        float run = 0.f;
#pragma unroll
        for (int c = 0; c < 16; ++c) {
            g_kvp[base + (size_t)c*4096] = run;
            run += v[c];
        }
    } else if (threadIdx.x < 64) {
        size_t kb = (size_t)bh * NCH * 64 + threadIdx.x;
        float v[16];
#pragma unroll
        for (int c = 0; c < 16; ++c) v[c] = g_ksm[kb + c*64];
        float run = 0.f;
#pragma unroll
        for (int c = 0; c < 16; ++c) {
            g_kpr[kb + c*64] = run;
            run += v[c];
        }
    }
}

// ---------------------------------------------------------------------------
// K3c: inter+intra chunk linear attention + fused per-row LN over D
// ---------------------------------------------------------------------------
__global__ void __launch_bounds__(256) k_linC(const float* __restrict__ ang,
                                              const float* __restrict__ anb)
{
    extern __shared__ float sm[];
    float* Qps = sm;               // [64][65]
    float* Kps = sm + 4160;
    float* Vss = sm + 2*4160;
    float* Sps = sm + 3*4160;
    float* Ps  = sm + 4*4160;
    float* kpre = sm + 5*4160;
    float* sg   = kpre + 64;
    float* sb   = sg + 64;

    const int ch = blockIdx.x, h = blockIdx.y, b = blockIdx.z;
    const int bh = b*HH + h;
    const int t0 = ch * 64;
    const int tid = threadIdx.x, tx = tid & 15, ty = tid >> 4;
    const float* Qb = g_q + (size_t)bh * (TT*DD);
    const float* Kb = g_k + (size_t)bh * (TT*DD);
    const float* Vb = g_v + (size_t)bh * (TT*DD);
    const size_t pbase = ((size_t)bh * NCH + ch) * 4096;

    for (int e = tid; e < 4096; e += 256) {
        int r = e >> 6, c = e & 63;
        Qps[r*65 + c] = elup(Qb[(size_t)(t0 + r)*64 + c] * 0.125f);
        Kps[r*65 + c] = elup(Kb[(size_t)(t0 + r)*64 + c] * 0.125f);
        Vss[r*65 + c] = Vb[(size_t)(t0 + r)*64 + c];
        Sps[r*65 + c] = g_kvp[pbase + e];
    }
    if (tid < 64) {
        kpre[tid] = g_kpr[((size_t)bh * NCH + ch)*64 + tid];
        sg[tid] = ang[tid];
        sb[tid] = anb[tid];
    }
    __syncthreads();

    float acc[4][4] = {};
    float sc[4][4]  = {};
    for (int d = 0; d < 64; ++d) {
        float qv[4], sv[4], kv[4];
#pragma unroll
        for (int i = 0; i < 4; ++i) qv[i] = Qps[(ty*4 + i)*65 + d];
#pragma unroll
        for (int j = 0; j < 4; ++j) sv[j] = Sps[d*65 + j*16 + tx];
#pragma unroll
        for (int j = 0; j < 4; ++j) kv[j] = Kps[(j*16 + tx)*65 + d];
#pragma unroll
        for (int i = 0; i < 4; ++i)
#pragma unroll
            for (int j = 0; j < 4; ++j) {
                acc[i][j] = fmaf(qv[i], sv[j], acc[i][j]);
                sc[i][j]  = fmaf(qv[i], kv[j], sc[i][j]);
            }
    }

    float den[4];
#pragma unroll
    for (int i = 0; i < 4; ++i) {
        int t_loc = ty*4 + i;
        float rs = 0.f;
#pragma unroll
        for (int j = 0; j < 4; ++j) {
            int s_loc = j*16 + tx;
            if (s_loc > t_loc) sc[i][j] = 0.f;
            rs += sc[i][j];
            Ps[t_loc*65 + s_loc] = sc[i][j];
        }
#pragma unroll
        for (int off = 8; off; off >>= 1)
            rs += __shfl_xor_sync(0xffffffffu, rs, off);
        float dq = 0.f;
        for (int d = 0; d < 64; ++d) dq = fmaf(Qps[t_loc*65 + d], kpre[d], dq);
        den[i] = dq + rs + 1e-4f;
    }
    __syncthreads();

    for (int s = 0; s < 64; ++s) {
        float pv[4], vv[4];
#pragma unroll
        for (int i = 0; i < 4; ++i) pv[i] = Ps[(ty*4 + i)*65 + s];
#pragma unroll
        for (int j = 0; j < 4; ++j) vv[j] = Vss[s*65 + j*16 + tx];
#pragma unroll
        for (int i = 0; i < 4; ++i)
#pragma unroll
            for (int j = 0; j < 4; ++j)
                acc[i][j] = fmaf(pv[i], vv[j], acc[i][j]);
    }

#pragma unroll
    for (int i = 0; i < 4; ++i) {
        float inv = 1.f / den[i];
        float y[4], smm = 0.f, sq = 0.f;
#pragma unroll
        for (int j = 0; j < 4; ++j) {
            y[j] = acc[i][j] * inv;
            smm += y[j];
            sq  += y[j]*y[j];
        }
#pragma unroll
        for (int off = 8; off; off >>= 1) {
            smm += __shfl_xor_sync(0xffffffffu, smm, off);
            sq  += __shfl_xor_sync(0xffffffffu, sq,  off);
        }
        float mean = smm * (1.f/64.f);
        float var  = sq * (1.f/64.f) - mean*mean;
        float rstd = rsqrtf(var + 1e-5f);
        int row = t0 + ty*4 + i;
#pragma unroll
        for (int j = 0; j < 4; ++j) {
            int e = j*16 + tx;
            g_yl[((size_t)bh * TT + row)*64 + e] = (y[j] - mean)*rstd*sg[e] + sb[e];
        }
    }
}

// ---------------------------------------------------------------------------
// K4: combine + out LN + pre LN + block mix + grid bilinear + reverse + bias
// ---------------------------------------------------------------------------
__device__ __forceinline__ float2 block_reduce2(float a, float b, float* red)
{
#pragma unroll
    for (int off = 16; off; off >>= 1) {
        a += __shfl_xor_sync(0xffffffffu, a, off);
        b += __shfl_xor_sync(0xffffffffu, b, off);
    }
    int w = threadIdx.x >> 5;
    if ((threadIdx.x & 31) == 0) { red[w] = a; red[8 + w] = b; }
    __syncthreads();
    float ta = 0.f, tb = 0.f;
#pragma unroll
    for (int i = 0; i < 8; ++i) { ta += red[i]; tb += red[8 + i]; }
    __syncthreads();
    return make_float2(ta, tb);
}

__global__ void __launch_bounds__(256) k_proj(const float* __restrict__ fgate,
                                              const float* __restrict__ og,
                                              const float* __restrict__ ob,
                                              const float* __restrict__ pg,
                                              const float* __restrict__ pb,
                                              const float* __restrict__ bw,
                                              const float* __restrict__ wrow,
                                              const float* __restrict__ wcol,
                                              const float* __restrict__ palpha,
                                              const float* __restrict__ pbias,
                                              float* __restrict__ out)
{
    extern __shared__ float sm[];
    float* xns   = sm;
    float* mixed = sm + 1024;
    float* zz    = sm + 2048;
    float* wcs   = sm + 3072;
    float* wrT   = sm + 4096;
    float* bws   = sm + 5120;
    float* red   = sm + 21504;

    const int t = blockIdx.x, b = blockIdx.y;
    const int tid = threadIdx.x;
    const float fg = fgate[0];
    const float alpha = 1.f / (1.f + __expf(-fg));
    const float pa = palpha[0];

    for (int i = tid; i < 16384; i += 256) bws[i] = bw[i];
    for (int i = tid; i < 1024; i += 256) {
        wcs[i] = wcol[i];
        wrT[(i & 31)*32 + (i >> 5)] = wrow[i];
    }

    float v[4];
    float s1 = 0.f, q1 = 0.f;
#pragma unroll
    for (int u = 0; u < 4; ++u) {
        int c = tid + u*256;
        int h = c >> 6, d = c & 63;
        size_t idx = ((size_t)(b*HH + h) * TT + t)*64 + d;
        float val = alpha * g_ys[idx] + (1.f - alpha) * g_yl[idx];
        v[u] = val;
        s1 += val; q1 += val*val;
    }
    float2 r1 = block_reduce2(s1, q1, red);
    float m1 = r1.x * (1.f/1024.f);
    float rs1 = rsqrtf(r1.y * (1.f/1024.f) - m1*m1 + 1e-5f);

    float w[4];
    float s2 = 0.f, q2 = 0.f;
#pragma unroll
    for (int u = 0; u < 4; ++u) {
        int c = tid + u*256;
        float val = (v[u] - m1) * rs1 * og[c] + ob[c];
        w[u] = val;
        s2 += val; q2 += val*val;
    }
    float2 r2 = block_reduce2(s2, q2, red);
    float m2 = r2.x * (1.f/1024.f);
    float rs2 = rsqrtf(r2.y * (1.f/1024.f) - m2*m2 + 1e-5f);
#pragma unroll
    for (int u = 0; u < 4; ++u) {
        int c = tid + u*256;
        xns[c] = (w[u] - m2) * rs2 * pg[c] + pb[c];
    }
    __syncthreads();

#pragma unroll
    for (int u = 0; u < 4; ++u) {
        int c = tid + u*256;
        int g = c >> 4, j = c & 15;
        float s = 0.f;
#pragma unroll
        for (int i = 0; i < 16; ++i)
            s = fmaf(xns[g*16 + i], bws[(g*16 + i)*16 + j], s);
        mixed[c] = s;

        int gi = c >> 5, cc = c & 31;
        float z = 0.f;
#pragma unroll
        for (int jj = 0; jj < 32; ++jj)
            z = fmaf(xns[gi*32 + jj], wcs[jj*32 + cc], z);
        zz[c] = z;
    }
    __syncthreads();

    float* orow = out + ((size_t)b * TT + t) * CC;
#pragma unroll
    for (int u = 0; u < 4; ++u) {
        int c = tid + u*256;
        int gi = c >> 5, r = c & 31;
        float z2 = 0.f;
#pragma unroll
        for (int cc = 0; cc < 32; ++cc)
            z2 = fmaf(zz[gi*32 + cc], wrT[cc*32 + r], z2);
        orow[c] = mixed[1023 - c] + pa * z2 + pbias[c];
    }
}

// ---------------------------------------------------------------------------
extern "C" void kernel_launch(void* const* d_in, const int* in_sizes, int n_in,
                              void* d_out, int out_size)
{
    (void)in_sizes; (void)n_in; (void)out_size;
    const float* x    = (const float*)d_in[0];
    const float* W    = (const float*)d_in[1];
    const float* cb   = (const float*)d_in[2];
    const float* fg   = (const float*)d_in[3];
    const float* ang  = (const float*)d_in[4];
    const float* anb  = (const float*)d_in[5];
    const float* og   = (const float*)d_in[6];
    const float* ob   = (const float*)d_in[7];
    const float* pg   = (const float*)d_in[8];
    const float* pb   = (const float*)d_in[9];
    const float* bw   = (const float*)d_in[10];
    const float* wr   = (const float*)d_in[11];
    const float* wc   = (const float*)d_in[12];
    const float* pa   = (const float*)d_in[13];
    const float* pbias= (const float*)d_in[14];
    float* out = (float*)d_out;

    cudaFuncSetAttribute(k_qkv,   cudaFuncAttributeMaxDynamicSharedMemorySize, 73728);
    cudaFuncSetAttribute(k_flash, cudaFuncAttributeMaxDynamicSharedMemorySize, 90880);
    cudaFuncSetAttribute(k_linC,  cudaFuncAttributeMaxDynamicSharedMemorySize, 83968);
    cudaFuncSetAttribute(k_proj,  cudaFuncAttributeMaxDynamicSharedMemorySize, 86080);

    k_cvt  <<<1184,               256>>>(x, W);
    k_qkv  <<<dim3(24, 16),       256, 73728>>>(cb);
    k_flash<<<dim3(16, 16, 2),    256, 90880>>>();
    k_linA <<<dim3(16, 16, 2),    256, 33280>>>();
    k_scan <<<dim3(17, 32),       256>>>();
    k_linC <<<dim3(16, 16, 2),    256, 83968>>>(ang, anb);
    k_proj <<<dim3(1024, 2),      256, 86080>>>(fg, og, ob, pg, pb, bw, wr, wc, pa, pbias, out);
}